// round 3
// baseline (speedup 1.0000x reference)
#include <cuda_runtime.h>

// Fixed shapes per reference: B=4096, IN=HID=8192, fp32
#define IN_DIM   8192
#define HID_DIM  8192
#define COL4     (IN_DIM / 4)                    // 2048 float4 per row
#define ROW_CHUNKS 64
#define ROWS_PER_CHUNK (HID_DIM / ROW_CHUNKS)    // 128
#define RD_GRID  888                             // 148 SMs x 6 resident blocks

// Device-global scratch (allocation-free rule: device globals allowed)
__device__ float g_partial[ROW_CHUNKS * IN_DIM];  // 2 MB
__device__ float g_wsum[IN_DIM];                  // 32 KB

// ---------------- Kernel 1: partial column sums of W [HID, IN] ----------------
// grid = (8, 64), block = 256. Proven 79.8% of HBM spec — unchanged from R1.
__global__ __launch_bounds__(256) void colsum_partial(const float* __restrict__ w) {
    const int col4 = blockIdx.x * 256 + threadIdx.x;        // 0..2047
    const int r0   = blockIdx.y * ROWS_PER_CHUNK;
    const float4* __restrict__ w4 = reinterpret_cast<const float4*>(w);

    float4 acc = make_float4(0.f, 0.f, 0.f, 0.f);
    #pragma unroll 8
    for (int r = 0; r < ROWS_PER_CHUNK; ++r) {
        float4 v = __ldg(&w4[(size_t)(r0 + r) * COL4 + col4]);
        acc.x += v.x; acc.y += v.y; acc.z += v.z; acc.w += v.w;
    }
    reinterpret_cast<float4*>(g_partial)[(size_t)blockIdx.y * COL4 + col4] = acc;
}

// ---------------- Kernel 2: reduce 64 partials -> g_wsum ----------------
__global__ __launch_bounds__(256) void reduce_partial() {
    const int col4 = blockIdx.x * 256 + threadIdx.x;
    const float4* __restrict__ p4 = reinterpret_cast<const float4*>(g_partial);
    float4 acc = make_float4(0.f, 0.f, 0.f, 0.f);
    #pragma unroll
    for (int c = 0; c < ROW_CHUNKS; ++c) {
        float4 v = p4[(size_t)c * COL4 + col4];
        acc.x += v.x; acc.y += v.y; acc.z += v.z; acc.w += v.w;
    }
    reinterpret_cast<float4*>(g_wsum)[col4] = acc;
}

// ---------------- Kernel 3: out[b] = 0.75 * dot(x[b], wsum) ----------------
// Persistent blocks: stage wsum in SMEM once, grid-stride over rows.
// Per row per thread: 8 fully-unrolled LDG.128 on x (MLP=8), FMAs against LDS.
__global__ __launch_bounds__(256, 6) void rowdot(const float* __restrict__ x,
                                                 float* __restrict__ out, int B) {
    __shared__ float4 s_w[COL4];          // 32 KB
    __shared__ float  warp_sums[2][8];    // double-buffered block reduce

    const int t    = threadIdx.x;
    const int lane = t & 31;
    const int wid  = t >> 5;

    // Stage wsum into shared memory (L2-resident source)
    const float4* __restrict__ w4 = reinterpret_cast<const float4*>(g_wsum);
    #pragma unroll
    for (int k = 0; k < COL4 / 256; ++k)
        s_w[t + k * 256] = __ldg(&w4[t + k * 256]);
    __syncthreads();

    int it = 0;
    for (int row = blockIdx.x; row < B; row += gridDim.x, ++it) {
        const float4* __restrict__ x4 =
            reinterpret_cast<const float4*>(x + (size_t)row * IN_DIM);

        float acc = 0.f;
        #pragma unroll
        for (int k = 0; k < COL4 / 256; ++k) {
            const int i = t + k * 256;
            float4 xv = __ldg(&x4[i]);
            float4 wv = s_w[i];
            acc = fmaf(xv.x, wv.x, acc);
            acc = fmaf(xv.y, wv.y, acc);
            acc = fmaf(xv.z, wv.z, acc);
            acc = fmaf(xv.w, wv.w, acc);
        }

        #pragma unroll
        for (int off = 16; off > 0; off >>= 1)
            acc += __shfl_xor_sync(0xFFFFFFFFu, acc, off);

        const int buf = it & 1;
        if (lane == 0) warp_sums[buf][wid] = acc;
        __syncthreads();

        if (wid == 0) {
            float v = (lane < 8) ? warp_sums[buf][lane] : 0.f;
            #pragma unroll
            for (int off = 4; off > 0; off >>= 1)
                v += __shfl_xor_sync(0xFFFFFFFFu, v, off);
            if (lane == 0) out[row] = v * 0.75f;   // (/2) * 1.5
        }
        // no second sync: next iteration writes the OTHER buffer, and the
        // following __syncthreads orders reuse two iterations out.
    }
}

extern "C" void kernel_launch(void* const* d_in, const int* in_sizes, int n_in,
                              void* d_out, int out_size) {
    const float* x = (const float*)d_in[0];   // [B, IN]
    const float* w = (const float*)d_in[1];   // [HID, IN]
    float* out = (float*)d_out;               // [B, 1]
    const int B = in_sizes[0] / IN_DIM;

    dim3 g1(COL4 / 256, ROW_CHUNKS);
    colsum_partial<<<g1, 256>>>(w);
    reduce_partial<<<COL4 / 256, 256>>>();
    rowdot<<<RD_GRID, 256>>>(x, out, B);
}

// round 4
// speedup vs baseline: 1.0519x; 1.0519x over previous
#include <cuda_runtime.h>

// Fixed shapes per reference: B=4096, IN=HID=8192, fp32
#define IN_DIM   8192
#define HID_DIM  8192
#define COL4     (IN_DIM / 4)                    // 2048 float4 per row
#define ROW_CHUNKS 64
#define ROWS_PER_CHUNK (HID_DIM / ROW_CHUNKS)    // 128
#define ROWS_PER_BLK 8                           // rowdot row tile

// Device-global scratch (allocation-free rule: device globals allowed)
__device__ float g_partial[ROW_CHUNKS * IN_DIM];  // 2 MB
__device__ float g_wsum[IN_DIM];                  // 32 KB

// ---------------- Kernel 1: partial column sums of W [HID, IN] ----------------
// grid = (8, 64), block = 256. Proven 79.8% of HBM spec — unchanged from R1.
__global__ __launch_bounds__(256) void colsum_partial(const float* __restrict__ w) {
    const int col4 = blockIdx.x * 256 + threadIdx.x;        // 0..2047
    const int r0   = blockIdx.y * ROWS_PER_CHUNK;
    const float4* __restrict__ w4 = reinterpret_cast<const float4*>(w);

    float4 acc = make_float4(0.f, 0.f, 0.f, 0.f);
    #pragma unroll 8
    for (int r = 0; r < ROWS_PER_CHUNK; ++r) {
        float4 v = __ldg(&w4[(size_t)(r0 + r) * COL4 + col4]);
        acc.x += v.x; acc.y += v.y; acc.z += v.z; acc.w += v.w;
    }
    reinterpret_cast<float4*>(g_partial)[(size_t)blockIdx.y * COL4 + col4] = acc;
}

// ---------------- Kernel 2: reduce 64 partials -> g_wsum ----------------
__global__ __launch_bounds__(256) void reduce_partial() {
    const int col4 = blockIdx.x * 256 + threadIdx.x;
    const float4* __restrict__ p4 = reinterpret_cast<const float4*>(g_partial);
    float4 acc = make_float4(0.f, 0.f, 0.f, 0.f);
    #pragma unroll
    for (int c = 0; c < ROW_CHUNKS; ++c) {
        float4 v = p4[(size_t)c * COL4 + col4];
        acc.x += v.x; acc.y += v.y; acc.z += v.z; acc.w += v.w;
    }
    reinterpret_cast<float4*>(g_wsum)[col4] = acc;
}

// ---------------- Kernel 3: out[b] = 0.75 * dot(x[b], wsum), 8 rows/block ----
// Per k-step: 1 wsum load amortized over 8 rows, 8 independent x LDG.128 in
// flight per thread. One block reduction for all 8 rows at the very end.
__global__ __launch_bounds__(256) void rowdot8(const float* __restrict__ x,
                                               float* __restrict__ out, int B) {
    const int t     = threadIdx.x;
    const int lane  = t & 31;
    const int wid   = t >> 5;
    const int rbase = blockIdx.x * ROWS_PER_BLK;

    const float4* __restrict__ w4 = reinterpret_cast<const float4*>(g_wsum);
    const float4* __restrict__ x4 = reinterpret_cast<const float4*>(x);

    float acc[ROWS_PER_BLK];
    #pragma unroll
    for (int r = 0; r < ROWS_PER_BLK; ++r) acc[r] = 0.f;

    #pragma unroll
    for (int k = 0; k < COL4 / 256; ++k) {           // 8 k-steps
        const int i = t + k * 256;
        float4 wv = __ldg(&w4[i]);                   // L2-resident, 1/8 per FMA-group

        float4 xv[ROWS_PER_BLK];
        #pragma unroll
        for (int r = 0; r < ROWS_PER_BLK; ++r)       // 8 independent streams -> MLP=8
            xv[r] = __ldg(&x4[(size_t)(rbase + r) * COL4 + i]);

        #pragma unroll
        for (int r = 0; r < ROWS_PER_BLK; ++r) {
            acc[r] = fmaf(xv[r].x, wv.x, acc[r]);
            acc[r] = fmaf(xv[r].y, wv.y, acc[r]);
            acc[r] = fmaf(xv[r].z, wv.z, acc[r]);
            acc[r] = fmaf(xv[r].w, wv.w, acc[r]);
        }
    }

    // Warp-reduce each of the 8 row accumulators
    #pragma unroll
    for (int r = 0; r < ROWS_PER_BLK; ++r) {
        #pragma unroll
        for (int off = 16; off > 0; off >>= 1)
            acc[r] += __shfl_xor_sync(0xFFFFFFFFu, acc[r], off);
    }

    // warp_sums[r][wid]: 8 rows x 8 warps
    __shared__ float warp_sums[ROWS_PER_BLK][8];
    if (lane == 0) {
        #pragma unroll
        for (int r = 0; r < ROWS_PER_BLK; ++r)
            warp_sums[r][wid] = acc[r];
    }
    __syncthreads();

    // Warp w finalizes row w (8 partials, reduce in lanes 0..7)
    float v = (lane < 8) ? warp_sums[wid][lane] : 0.f;
    #pragma unroll
    for (int off = 4; off > 0; off >>= 1)
        v += __shfl_xor_sync(0xFFFFFFFFu, v, off);
    if (lane == 0 && rbase + wid < B)
        out[rbase + wid] = v * 0.75f;                // (/2) * 1.5
}

extern "C" void kernel_launch(void* const* d_in, const int* in_sizes, int n_in,
                              void* d_out, int out_size) {
    const float* x = (const float*)d_in[0];   // [B, IN]
    const float* w = (const float*)d_in[1];   // [HID, IN]
    float* out = (float*)d_out;               // [B, 1]
    const int B = in_sizes[0] / IN_DIM;

    dim3 g1(COL4 / 256, ROW_CHUNKS);
    colsum_partial<<<g1, 256>>>(w);
    reduce_partial<<<COL4 / 256, 256>>>();
    rowdot8<<<(B + ROWS_PER_BLK - 1) / ROWS_PER_BLK, 256>>>(x, out, B);
}